// round 1
// baseline (speedup 1.0000x reference)
#include <cuda_runtime.h>
#include <cuda_bf16.h>
#include <math.h>

// Problem constants
#define NN      8000
#define NFEAT   512
#define NHID    128
#define NCLS    64
#define CAP     96        // max neighbors per row (E[deg]=16, sigma~4; 96 = 20 sigma)
#define EPS     1e-12f

// ---------------- scratch (device globals; no allocation allowed) ------------
__device__ float g_h     [NN * NHID];   // h = relu(x@W0+b0) == h0
__device__ float g_li0   [NN * NHID];
__device__ float g_li1   [NN * NHID];
__device__ float g_yhat  [NN * NCLS];
__device__ float g_pseudo[NN * NCLS];
__device__ int   g_cols  [NN * CAP];
__device__ float g_w     [NN * CAP];
__device__ int   g_deg   [NN];

// ---------------- GEMM1: h = relu(x @ W0 + b0)  [8000x512]@[512x128] ---------
// BM=64, BN=128, BK=16, 256 threads (16x16), thread tile 4x8
__global__ void gemm1_kernel(const float* __restrict__ x,
                             const float* __restrict__ W0,
                             const float* __restrict__ b0) {
    __shared__ float As[64 * 17];      // [row][k] padded
    __shared__ float Bs[16 * 128];     // [k][col]

    const int tid = threadIdx.x;
    const int tx = tid & 15;           // 0..15 -> col group (8 cols)
    const int ty = tid >> 4;           // 0..15 -> row group (4 rows)
    const int m0 = blockIdx.x * 64;

    float acc[4][8];
#pragma unroll
    for (int m = 0; m < 4; m++)
#pragma unroll
        for (int n = 0; n < 8; n++) acc[m][n] = 0.0f;

    for (int k0 = 0; k0 < NFEAT; k0 += 16) {
        // load A tile: 64x16, one float4 per thread
        {
            int row = tid >> 2;
            int c4  = (tid & 3) << 2;
            float4 v = *reinterpret_cast<const float4*>(
                x + (size_t)(m0 + row) * NFEAT + k0 + c4);
            As[row * 17 + c4 + 0] = v.x;
            As[row * 17 + c4 + 1] = v.y;
            As[row * 17 + c4 + 2] = v.z;
            As[row * 17 + c4 + 3] = v.w;
        }
        // load B tile: 16x128, two float4 per thread
        {
            int r = tid >> 4;          // 0..15
            int c = (tid & 15) << 3;   // 0,8,...,120
#pragma unroll
            for (int i = 0; i < 2; i++) {
                float4 v = *reinterpret_cast<const float4*>(
                    W0 + (size_t)(k0 + r) * NHID + c + i * 4);
                *reinterpret_cast<float4*>(&Bs[r * 128 + c + i * 4]) = v;
            }
        }
        __syncthreads();

#pragma unroll
        for (int kk = 0; kk < 16; kk++) {
            float a[4], b[8];
#pragma unroll
            for (int m = 0; m < 4; m++) a[m] = As[(ty * 4 + m) * 17 + kk];
#pragma unroll
            for (int n = 0; n < 8; n++) b[n] = Bs[kk * 128 + tx * 8 + n];
#pragma unroll
            for (int m = 0; m < 4; m++)
#pragma unroll
                for (int n = 0; n < 8; n++) acc[m][n] += a[m] * b[n];
        }
        __syncthreads();
    }

    float bb[8];
#pragma unroll
    for (int n = 0; n < 8; n++) bb[n] = b0[tx * 8 + n];

#pragma unroll
    for (int m = 0; m < 4; m++) {
        int row = m0 + ty * 4 + m;
#pragma unroll
        for (int n = 0; n < 8; n++) {
            float v = acc[m][n] + bb[n];
            g_h[(size_t)row * NHID + tx * 8 + n] = fmaxf(v, 0.0f);
        }
    }
}

// ---------------- sparse extraction: warp-per-row, ballot prefix -------------
__global__ void extract_adj_kernel(const float* __restrict__ adj) {
    int warp = (blockIdx.x * blockDim.x + threadIdx.x) >> 5;
    if (warp >= NN) return;
    int lane = threadIdx.x & 31;
    const float* row = adj + (size_t)warp * NN;
    int base = 0;
    for (int c0 = 0; c0 < NN; c0 += 32) {
        float v = row[c0 + lane];
        unsigned m = __ballot_sync(0xffffffffu, v != 0.0f);
        if (v != 0.0f) {
            int pos = base + __popc(m & ((1u << lane) - 1u));
            if (pos < CAP) g_cols[warp * CAP + pos] = c0 + lane;
        }
        base += __popc(m);
    }
    if (lane == 0) g_deg[warp] = base < CAP ? base : CAP;
}

// ---------------- Pseudo = h @ W1 + b1  [8000x128]@[128x64] ------------------
__global__ void gemm_pseudo_kernel(const float* __restrict__ W1,
                                   const float* __restrict__ b1) {
    int ry = threadIdx.y, c = threadIdx.x;
    int row = blockIdx.x * 4 + ry;
    __shared__ float hr[4][128];
    hr[ry][c]      = g_h[(size_t)row * NHID + c];
    hr[ry][c + 64] = g_h[(size_t)row * NHID + c + 64];
    __syncthreads();
    float acc = b1[c];
#pragma unroll 8
    for (int k = 0; k < NHID; k++) acc += hr[ry][k] * W1[k * NCLS + c];
    g_pseudo[(size_t)row * NCLS + c] = acc;
}

// ---------------- label injection (duplicate-safe, deterministic) ------------
__global__ void inject_kernel(const int* __restrict__ idx,
                              const float* __restrict__ y_label) {
    int r = idx[blockIdx.x];
    int c = threadIdx.x;
    float add = 0.1f * y_label[(size_t)r * NCLS + c];
    atomicAdd(&g_pseudo[(size_t)r * NCLS + c], add);
}

// ---------------- softmax rows of Pseudo -> yhat; also emit Pseudo -----------
__global__ void softmax_kernel(float* __restrict__ out_pseudo) {
    int ry = threadIdx.y, c = threadIdx.x;
    int row = blockIdx.x * 4 + ry;
    float v = g_pseudo[(size_t)row * NCLS + c];
    out_pseudo[(size_t)row * NCLS + c] = v;

    __shared__ float sm[4][2];
    int wu = c >> 5, lane = c & 31;

    float m = v;
#pragma unroll
    for (int o = 16; o; o >>= 1) m = fmaxf(m, __shfl_xor_sync(0xffffffffu, m, o));
    if (lane == 0) sm[ry][wu] = m;
    __syncthreads();
    m = fmaxf(sm[ry][0], sm[ry][1]);
    __syncthreads();

    float e = expf(v - m);
    float s = e;
#pragma unroll
    for (int o = 16; o; o >>= 1) s += __shfl_xor_sync(0xffffffffu, s, o);
    if (lane == 0) sm[ry][wu] = s;
    __syncthreads();
    s = sm[ry][0] + sm[ry][1];
    g_yhat[(size_t)row * NCLS + c] = e / s;
}

// ---------------- edge weights (loop-invariant across layers) ----------------
// w_ij = dot(yhat_i, yhat_j); normalized by row L1 sum (all nonneg)
__global__ void edge_weights_kernel() {
    int row = blockIdx.x;
    __shared__ float yi[NCLS];
    __shared__ float wts[CAP];
    __shared__ float ssum;
    int t = threadIdx.x;               // 128 threads, 4 warps
    if (t < NCLS) yi[t] = g_yhat[(size_t)row * NCLS + t];
    __syncthreads();
    int deg = g_deg[row];
    int w = t >> 5, lane = t & 31;
    for (int n = w; n < deg; n += 4) {
        int j = g_cols[row * CAP + n];
        const float* yj = g_yhat + (size_t)j * NCLS;
        float p = yi[lane] * yj[lane] + yi[lane + 32] * yj[lane + 32];
#pragma unroll
        for (int o = 16; o; o >>= 1) p += __shfl_down_sync(0xffffffffu, p, o);
        if (lane == 0) wts[n] = p;
    }
    __syncthreads();
    if (t == 0) {
        float s = 0.0f;
        for (int n = 0; n < deg; n++) s += wts[n];
        ssum = fmaxf(s, EPS);
    }
    __syncthreads();
    if (t < deg) g_w[row * CAP + t] = wts[t] / ssum;
}

// ---------------- one propagation layer: SpMM + residual + L2 norm -----------
__global__ void propagate_kernel(int step) {
    const float* li_in = (step == 0) ? g_h : g_li0;
    float* li_out      = (step == 0) ? g_li0 : g_li1;
    int row = blockIdx.x;
    __shared__ int   cs[CAP];
    __shared__ float ws[CAP];
    __shared__ float red[128];
    int t = threadIdx.x;
    int deg = g_deg[row];
    if (t < deg) { cs[t] = g_cols[row * CAP + t]; ws[t] = g_w[row * CAP + t]; }
    __syncthreads();
    float s = 0.0f;
    for (int n = 0; n < deg; n++) s += ws[n] * li_in[(size_t)cs[n] * NHID + t];
    float v = 0.9f * s + 0.1f * g_h[(size_t)row * NHID + t];
    red[t] = v * v;
    __syncthreads();
#pragma unroll
    for (int st = 64; st; st >>= 1) {
        if (t < st) red[t] += red[t + st];
        __syncthreads();
    }
    float nrm = fmaxf(sqrtf(red[0]), EPS);
    li_out[(size_t)row * NHID + t] = v / nrm;
}

// ---------------- final: out = log_softmax(li @ W2 + b2) ---------------------
__global__ void final_kernel(const float* __restrict__ W2,
                             const float* __restrict__ b2,
                             float* __restrict__ out) {
    int ry = threadIdx.y, c = threadIdx.x;
    int row = blockIdx.x * 4 + ry;
    __shared__ float lr[4][128];
    lr[ry][c]      = g_li1[(size_t)row * NHID + c];
    lr[ry][c + 64] = g_li1[(size_t)row * NHID + c + 64];
    __syncthreads();
    float acc = b2[c];
#pragma unroll 8
    for (int k = 0; k < NHID; k++) acc += lr[ry][k] * W2[k * NCLS + c];

    __shared__ float sm[4][2];
    int wu = c >> 5, lane = c & 31;
    float m = acc;
#pragma unroll
    for (int o = 16; o; o >>= 1) m = fmaxf(m, __shfl_xor_sync(0xffffffffu, m, o));
    if (lane == 0) sm[ry][wu] = m;
    __syncthreads();
    m = fmaxf(sm[ry][0], sm[ry][1]);
    __syncthreads();

    float sh = acc - m;
    float e = expf(sh);
    float s = e;
#pragma unroll
    for (int o = 16; o; o >>= 1) s += __shfl_xor_sync(0xffffffffu, s, o);
    if (lane == 0) sm[ry][wu] = s;
    __syncthreads();
    s = sm[ry][0] + sm[ry][1];
    out[(size_t)row * NCLS + c] = sh - logf(s);
}

// ---------------- launch ------------------------------------------------------
extern "C" void kernel_launch(void* const* d_in, const int* in_sizes, int n_in,
                              void* d_out, int out_size) {
    const float* x      = (const float*)d_in[0];
    const float* adj    = (const float*)d_in[1];
    const float* y_lab  = (const float*)d_in[2];
    const int*   idx_tr = (const int*)  d_in[3];
    const float* W0     = (const float*)d_in[4];
    const float* b0     = (const float*)d_in[5];
    const float* W1     = (const float*)d_in[6];
    const float* b1     = (const float*)d_in[7];
    const float* W2     = (const float*)d_in[8];
    const float* b2     = (const float*)d_in[9];
    float* out = (float*)d_out;

    // h = relu(x@W0+b0)                      (125 blocks x 256 thr)
    gemm1_kernel<<<NN / 64, 256>>>(x, W0, b0);
    // sparse structure of adj                (8000 warps)
    extract_adj_kernel<<<NN / 8, 256>>>(adj);
    // Pseudo = h@W1+b1
    gemm_pseudo_kernel<<<NN / 4, dim3(64, 4)>>>(W1, b1);
    // Pseudo[idx_train] += 0.1*y_label[idx_train]
    inject_kernel<<<500, NCLS>>>(idx_tr, y_lab);
    // yhat = softmax(Pseudo); emit Pseudo (output #2)
    softmax_kernel<<<NN / 4, dim3(64, 4)>>>(out + (size_t)NN * NCLS);
    // normalized edge weights (shared by both layers)
    edge_weights_kernel<<<NN, 128>>>();
    // two propagation layers
    propagate_kernel<<<NN, NHID>>>(0);
    propagate_kernel<<<NN, NHID>>>(1);
    // log_softmax(li@W2+b2)  (output #1)
    final_kernel<<<NN / 4, dim3(64, 4)>>>(W2, b2, out);
}

// round 2
// speedup vs baseline: 1.1715x; 1.1715x over previous
#include <cuda_runtime.h>
#include <cuda_bf16.h>
#include <math.h>

// Problem constants
#define NN      8000
#define NFEAT   512
#define NHID    128
#define NCLS    64
#define CAP     96        // max neighbors per row (E[deg]=16; 96 = huge margin)
#define EPS     1e-12f

#define AST 20            // As smem stride (16 + 4 pad)
#define BST 136           // Bs smem stride (128 + 8 pad -> conflict-free frag loads)

// ---------------- scratch (device globals; no allocation allowed) ------------
__device__ float g_h     [NN * NHID];   // h = relu(x@W0+b0) == h0
__device__ float g_li0   [NN * NHID];
__device__ float g_li1   [NN * NHID];
__device__ float g_yhat  [NN * NCLS];
__device__ float g_pseudo[NN * NCLS];
__device__ int   g_cols  [NN * CAP];
__device__ float g_w     [NN * CAP];
__device__ int   g_deg   [NN];

// ---------------- helpers ----------------------------------------------------
__device__ __forceinline__ unsigned f2tf(float f) {
    unsigned u;
    asm("cvt.rna.tf32.f32 %0, %1;" : "=r"(u) : "f"(f));
    return u;
}

#define MMA_TF32(cc, a, b0_, b1_)                                              \
    asm volatile(                                                              \
        "mma.sync.aligned.m16n8k8.row.col.f32.tf32.tf32.f32 "                  \
        "{%0,%1,%2,%3}, {%4,%5,%6,%7}, {%8,%9}, {%0,%1,%2,%3};"                \
        : "+f"(cc[0]), "+f"(cc[1]), "+f"(cc[2]), "+f"(cc[3])                   \
        : "r"(a[0]), "r"(a[1]), "r"(a[2]), "r"(a[3]), "r"(b0_), "r"(b1_))

// ---------------- GEMM1 (tensor): h = relu(x @ W0 + b0) ----------------------
// [8000x512]@[512x128], BM=64, BN=128, BK=16, 128 threads (4 warps),
// warp tile 32x64, tf32 hi/lo split (3 MMAs per tile) for fp32-grade accuracy.
__global__ __launch_bounds__(128) void gemm1_tc(const float* __restrict__ x,
                                                const float* __restrict__ W0,
                                                const float* __restrict__ b0) {
    __shared__ unsigned Ah[64 * AST], Al[64 * AST];
    __shared__ unsigned Bh[16 * BST], Bl[16 * BST];

    const int tid  = threadIdx.x;
    const int warp = tid >> 5;
    const int lane = tid & 31;
    const int m0   = blockIdx.x * 64;
    const int wm   = (warp & 1) * 32;    // warp M offset
    const int wn   = (warp >> 1) * 64;   // warp N offset

    float c[2][8][4];
#pragma unroll
    for (int mt = 0; mt < 2; mt++)
#pragma unroll
        for (int nt = 0; nt < 8; nt++)
#pragma unroll
            for (int r = 0; r < 4; r++) c[mt][nt][r] = 0.0f;

    // gmem prefetch mapping
    const int ra = tid >> 1, ca = (tid & 1) * 8;     // A: 64x16, 8 elems/thread
    const int rb = tid >> 3, cb = (tid & 7) * 16;    // B: 16x128, 16 elems/thread
    float4 xa[2], wb[4];

    // prefetch tile 0
    {
        const float* xp = x + (size_t)(m0 + ra) * NFEAT + ca;
        xa[0] = *(const float4*)(xp);
        xa[1] = *(const float4*)(xp + 4);
        const float* wp = W0 + (size_t)rb * NHID + cb;
#pragma unroll
        for (int i = 0; i < 4; i++) wb[i] = *(const float4*)(wp + i * 4);
    }

    for (int it = 0; it < 32; it++) {
        // store prefetched tile to smem (split hi/lo)
        {
            const float* av = (const float*)xa;
#pragma unroll
            for (int j = 0; j < 8; j++) {
                float v  = av[j];
                unsigned hb = f2tf(v);
                Ah[ra * AST + ca + j] = hb;
                Al[ra * AST + ca + j] = f2tf(v - __uint_as_float(hb));
            }
            const float* bv = (const float*)wb;
#pragma unroll
            for (int j = 0; j < 16; j++) {
                float v  = bv[j];
                unsigned hb = f2tf(v);
                Bh[rb * BST + cb + j] = hb;
                Bl[rb * BST + cb + j] = f2tf(v - __uint_as_float(hb));
            }
        }
        __syncthreads();

        // prefetch next tile
        if (it < 31) {
            int k0 = (it + 1) * 16;
            const float* xp = x + (size_t)(m0 + ra) * NFEAT + k0 + ca;
            xa[0] = *(const float4*)(xp);
            xa[1] = *(const float4*)(xp + 4);
            const float* wp = W0 + (size_t)(k0 + rb) * NHID + cb;
#pragma unroll
            for (int i = 0; i < 4; i++) wb[i] = *(const float4*)(wp + i * 4);
        }

        // compute: 2 k-steps of m16n8k8
#pragma unroll
        for (int ks = 0; ks < 16; ks += 8) {
            unsigned ah[2][4], al[2][4];
            const int arow = wm + (lane >> 2);
            const int ac   = ks + (lane & 3);
#pragma unroll
            for (int mt = 0; mt < 2; mt++) {
                int r = arow + mt * 16;
                ah[mt][0] = Ah[r * AST + ac];
                ah[mt][1] = Ah[(r + 8) * AST + ac];
                ah[mt][2] = Ah[r * AST + ac + 4];
                ah[mt][3] = Ah[(r + 8) * AST + ac + 4];
                al[mt][0] = Al[r * AST + ac];
                al[mt][1] = Al[(r + 8) * AST + ac];
                al[mt][2] = Al[r * AST + ac + 4];
                al[mt][3] = Al[(r + 8) * AST + ac + 4];
            }
#pragma unroll
            for (int nt = 0; nt < 8; nt++) {
                const int bn = wn + nt * 8 + (lane >> 2);
                const int bk = ks + (lane & 3);
                unsigned bh0 = Bh[bk * BST + bn];
                unsigned bh1 = Bh[(bk + 4) * BST + bn];
                unsigned bl0 = Bl[bk * BST + bn];
                unsigned bl1 = Bl[(bk + 4) * BST + bn];
#pragma unroll
                for (int mt = 0; mt < 2; mt++) {
                    MMA_TF32(c[mt][nt], ah[mt], bh0, bh1);   // hi*hi
                    MMA_TF32(c[mt][nt], ah[mt], bl0, bl1);   // hi*lo
                    MMA_TF32(c[mt][nt], al[mt], bh0, bh1);   // lo*hi
                }
            }
        }
        __syncthreads();
    }

    // epilogue: bias + relu
#pragma unroll
    for (int nt = 0; nt < 8; nt++) {
        int col = wn + nt * 8 + 2 * (lane & 3);
        float bias0 = b0[col], bias1 = b0[col + 1];
#pragma unroll
        for (int mt = 0; mt < 2; mt++) {
            int r = m0 + wm + mt * 16 + (lane >> 2);
            g_h[(size_t)r * NHID + col]           = fmaxf(c[mt][nt][0] + bias0, 0.0f);
            g_h[(size_t)r * NHID + col + 1]       = fmaxf(c[mt][nt][1] + bias1, 0.0f);
            g_h[(size_t)(r + 8) * NHID + col]     = fmaxf(c[mt][nt][2] + bias0, 0.0f);
            g_h[(size_t)(r + 8) * NHID + col + 1] = fmaxf(c[mt][nt][3] + bias1, 0.0f);
        }
    }
}

// ---------------- sparse extraction: warp-per-row, float4 + shfl-scan --------
__global__ void extract_adj_kernel(const float* __restrict__ adj) {
    int row_id = (blockIdx.x * blockDim.x + threadIdx.x) >> 5;
    if (row_id >= NN) return;
    int lane = threadIdx.x & 31;
    const float* row = adj + (size_t)row_id * NN;
    int base = 0;
    // 8000 = 62*128 + 64
    for (int c0 = 0; c0 < 7936; c0 += 128) {
        float4 v = *(const float4*)(row + c0 + lane * 4);
        unsigned m4 = (v.x != 0.0f) | ((v.y != 0.0f) << 1) |
                      ((v.z != 0.0f) << 2) | ((v.w != 0.0f) << 3);
        int nz = __popc(m4);
        int sc = nz;
#pragma unroll
        for (int o = 1; o < 32; o <<= 1) {
            int t = __shfl_up_sync(0xffffffffu, sc, o);
            if (lane >= o) sc += t;
        }
        int total = __shfl_sync(0xffffffffu, sc, 31);
        if (m4) {
            int p = base + sc - nz;
            int col = c0 + lane * 4;
            if (m4 & 1) { if (p < CAP) g_cols[row_id * CAP + p] = col;     p++; }
            if (m4 & 2) { if (p < CAP) g_cols[row_id * CAP + p] = col + 1; p++; }
            if (m4 & 4) { if (p < CAP) g_cols[row_id * CAP + p] = col + 2; p++; }
            if (m4 & 8) { if (p < CAP) g_cols[row_id * CAP + p] = col + 3; }
        }
        base += total;
    }
    // tail: 64 columns
    {
        float2 v = *(const float2*)(row + 7936 + lane * 2);
        unsigned m2 = (v.x != 0.0f) | ((v.y != 0.0f) << 1);
        int nz = __popc(m2);
        int sc = nz;
#pragma unroll
        for (int o = 1; o < 32; o <<= 1) {
            int t = __shfl_up_sync(0xffffffffu, sc, o);
            if (lane >= o) sc += t;
        }
        int total = __shfl_sync(0xffffffffu, sc, 31);
        if (m2) {
            int p = base + sc - nz;
            int col = 7936 + lane * 2;
            if (m2 & 1) { if (p < CAP) g_cols[row_id * CAP + p] = col;     p++; }
            if (m2 & 2) { if (p < CAP) g_cols[row_id * CAP + p] = col + 1; }
        }
        base += total;
    }
    if (lane == 0) g_deg[row_id] = base < CAP ? base : CAP;
}

// ---------------- Pseudo = h @ W1 + b1  [8000x128]@[128x64] ------------------
__global__ void gemm_pseudo_kernel(const float* __restrict__ W1,
                                   const float* __restrict__ b1) {
    int ry = threadIdx.y, c = threadIdx.x;
    int row = blockIdx.x * 4 + ry;
    __shared__ float hr[4][128];
    hr[ry][c]      = g_h[(size_t)row * NHID + c];
    hr[ry][c + 64] = g_h[(size_t)row * NHID + c + 64];
    __syncthreads();
    float acc = b1[c];
#pragma unroll 8
    for (int k = 0; k < NHID; k++) acc += hr[ry][k] * W1[k * NCLS + c];
    g_pseudo[(size_t)row * NCLS + c] = acc;
}

// ---------------- label injection (duplicate-safe, deterministic) ------------
__global__ void inject_kernel(const int* __restrict__ idx,
                              const float* __restrict__ y_label) {
    int r = idx[blockIdx.x];
    int c = threadIdx.x;
    float add = 0.1f * y_label[(size_t)r * NCLS + c];
    atomicAdd(&g_pseudo[(size_t)r * NCLS + c], add);
}

// ---------------- softmax rows of Pseudo -> yhat; also emit Pseudo -----------
__global__ void softmax_kernel(float* __restrict__ out_pseudo) {
    int ry = threadIdx.y, c = threadIdx.x;
    int row = blockIdx.x * 4 + ry;
    float v = g_pseudo[(size_t)row * NCLS + c];
    out_pseudo[(size_t)row * NCLS + c] = v;

    __shared__ float sm[4][2];
    int wu = c >> 5, lane = c & 31;

    float m = v;
#pragma unroll
    for (int o = 16; o; o >>= 1) m = fmaxf(m, __shfl_xor_sync(0xffffffffu, m, o));
    if (lane == 0) sm[ry][wu] = m;
    __syncthreads();
    m = fmaxf(sm[ry][0], sm[ry][1]);
    __syncthreads();

    float e = expf(v - m);
    float s = e;
#pragma unroll
    for (int o = 16; o; o >>= 1) s += __shfl_xor_sync(0xffffffffu, s, o);
    if (lane == 0) sm[ry][wu] = s;
    __syncthreads();
    s = sm[ry][0] + sm[ry][1];
    g_yhat[(size_t)row * NCLS + c] = e / s;
}

// ---------------- edge weights (loop-invariant across layers) ----------------
__global__ void edge_weights_kernel() {
    int row = blockIdx.x;
    __shared__ float yi[NCLS];
    __shared__ float wts[CAP];
    __shared__ float ssum;
    int t = threadIdx.x;               // 128 threads, 4 warps
    if (t < NCLS) yi[t] = g_yhat[(size_t)row * NCLS + t];
    __syncthreads();
    int deg = g_deg[row];
    int w = t >> 5, lane = t & 31;
    for (int n = w; n < deg; n += 4) {
        int j = g_cols[row * CAP + n];
        const float* yj = g_yhat + (size_t)j * NCLS;
        float p = yi[lane] * yj[lane] + yi[lane + 32] * yj[lane + 32];
#pragma unroll
        for (int o = 16; o; o >>= 1) p += __shfl_down_sync(0xffffffffu, p, o);
        if (lane == 0) wts[n] = p;
    }
    __syncthreads();
    if (t == 0) {
        float s = 0.0f;
        for (int n = 0; n < deg; n++) s += wts[n];
        ssum = fmaxf(s, EPS);
    }
    __syncthreads();
    if (t < deg) g_w[row * CAP + t] = wts[t] / ssum;
}

// ---------------- one propagation layer: SpMM + residual + L2 norm -----------
__global__ void propagate_kernel(int step) {
    const float* li_in = (step == 0) ? g_h : g_li0;
    float* li_out      = (step == 0) ? g_li0 : g_li1;
    int row = blockIdx.x;
    __shared__ int   cs[CAP];
    __shared__ float ws[CAP];
    __shared__ float red[128];
    int t = threadIdx.x;
    int deg = g_deg[row];
    if (t < deg) { cs[t] = g_cols[row * CAP + t]; ws[t] = g_w[row * CAP + t]; }
    __syncthreads();
    float s = 0.0f;
    for (int n = 0; n < deg; n++) s += ws[n] * li_in[(size_t)cs[n] * NHID + t];
    float v = 0.9f * s + 0.1f * g_h[(size_t)row * NHID + t];
    red[t] = v * v;
    __syncthreads();
#pragma unroll
    for (int st = 64; st; st >>= 1) {
        if (t < st) red[t] += red[t + st];
        __syncthreads();
    }
    float nrm = fmaxf(sqrtf(red[0]), EPS);
    li_out[(size_t)row * NHID + t] = v / nrm;
}

// ---------------- final: out = log_softmax(li @ W2 + b2) ---------------------
__global__ void final_kernel(const float* __restrict__ W2,
                             const float* __restrict__ b2,
                             float* __restrict__ out) {
    int ry = threadIdx.y, c = threadIdx.x;
    int row = blockIdx.x * 4 + ry;
    __shared__ float lr[4][128];
    lr[ry][c]      = g_li1[(size_t)row * NHID + c];
    lr[ry][c + 64] = g_li1[(size_t)row * NHID + c + 64];
    __syncthreads();
    float acc = b2[c];
#pragma unroll 8
    for (int k = 0; k < NHID; k++) acc += lr[ry][k] * W2[k * NCLS + c];

    __shared__ float sm[4][2];
    int wu = c >> 5, lane = c & 31;
    float m = acc;
#pragma unroll
    for (int o = 16; o; o >>= 1) m = fmaxf(m, __shfl_xor_sync(0xffffffffu, m, o));
    if (lane == 0) sm[ry][wu] = m;
    __syncthreads();
    m = fmaxf(sm[ry][0], sm[ry][1]);
    __syncthreads();

    float sh = acc - m;
    float e = expf(sh);
    float s = e;
#pragma unroll
    for (int o = 16; o; o >>= 1) s += __shfl_xor_sync(0xffffffffu, s, o);
    if (lane == 0) sm[ry][wu] = s;
    __syncthreads();
    s = sm[ry][0] + sm[ry][1];
    out[(size_t)row * NCLS + c] = sh - logf(s);
}

// ---------------- launch ------------------------------------------------------
extern "C" void kernel_launch(void* const* d_in, const int* in_sizes, int n_in,
                              void* d_out, int out_size) {
    const float* x      = (const float*)d_in[0];
    const float* adj    = (const float*)d_in[1];
    const float* y_lab  = (const float*)d_in[2];
    const int*   idx_tr = (const int*)  d_in[3];
    const float* W0     = (const float*)d_in[4];
    const float* b0     = (const float*)d_in[5];
    const float* W1     = (const float*)d_in[6];
    const float* b1     = (const float*)d_in[7];
    const float* W2     = (const float*)d_in[8];
    const float* b2     = (const float*)d_in[9];
    float* out = (float*)d_out;

    // h = relu(x@W0+b0) on tensor cores (tf32 split)
    gemm1_tc<<<NN / 64, 128>>>(x, W0, b0);
    // sparse structure of adj
    extract_adj_kernel<<<NN / 8, 256>>>(adj);
    // Pseudo = h@W1+b1
    gemm_pseudo_kernel<<<NN / 4, dim3(64, 4)>>>(W1, b1);
    // Pseudo[idx_train] += 0.1*y_label[idx_train]
    inject_kernel<<<500, NCLS>>>(idx_tr, y_lab);
    // yhat = softmax(Pseudo); emit Pseudo (output #2)
    softmax_kernel<<<NN / 4, dim3(64, 4)>>>(out + (size_t)NN * NCLS);
    // normalized edge weights (shared by both layers)
    edge_weights_kernel<<<NN, 128>>>();
    // two propagation layers
    propagate_kernel<<<NN, NHID>>>(0);
    propagate_kernel<<<NN, NHID>>>(1);
    // log_softmax(li@W2+b2)  (output #1)
    final_kernel<<<NN / 4, dim3(64, 4)>>>(W2, b2, out);
}